// round 15
// baseline (speedup 1.0000x reference)
#include <cuda_runtime.h>

// out[row, :] = W[ids[row], :]
// W: [50257, 1024] fp32, ids: [32768] int32, out: [32768, 1024] fp32
//
// Id-ordered gather: rows are processed in bucket-of-id order (bucket =
// id >> 7, 393 buckets) so duplicate ids are processed concurrently (L2
// hits) and distinct-row reads sweep the weight table near-sequentially
// (DRAM row-buffer locality). Stores are per-row contiguous regardless of
// processing order, so the permutation is free on the write side.
// Pipeline: zero-hist -> histogram -> scan -> scatter(perm) -> gather.

#define N_ROWS 32768
#define N_BUCKETS 512          // id>>7 max = 50256>>7 = 392 < 512

__device__ int g_hist[N_BUCKETS];
__device__ int g_off[N_BUCKETS];
__device__ unsigned long long g_perm[N_ROWS];   // (id << 32) | row

__global__ void k_zero() {
    g_hist[threadIdx.x] = 0;
}

__global__ void k_hist(const int* __restrict__ ids) {
    const int i = blockIdx.x * blockDim.x + threadIdx.x;
    if (i < N_ROWS) atomicAdd(&g_hist[ids[i] >> 7], 1);
}

__global__ void k_scan() {   // 1 block, N_BUCKETS threads: exclusive scan
    __shared__ int s[N_BUCKETS];
    const int t = threadIdx.x;
    const int h = g_hist[t];
    s[t] = h;
    __syncthreads();
    for (int d = 1; d < N_BUCKETS; d <<= 1) {
        int v = (t >= d) ? s[t - d] : 0;
        __syncthreads();
        s[t] += v;
        __syncthreads();
    }
    g_off[t] = s[t] - h;     // exclusive prefix
}

__global__ void k_scatter(const int* __restrict__ ids) {
    const int i = blockIdx.x * blockDim.x + threadIdx.x;
    if (i < N_ROWS) {
        const int id = ids[i];
        const int pos = atomicAdd(&g_off[id >> 7], 1);
        g_perm[pos] = ((unsigned long long)(unsigned)id << 32) | (unsigned)i;
    }
}

// 8 perm entries per CTA, 256 threads, 8 independent 128-bit gathers.
__global__ void __launch_bounds__(256)
k_gather(const float4* __restrict__ w, float4* __restrict__ out)
{
    __shared__ unsigned long long sp[8];
    const int t = threadIdx.x;
    if (t < 8) sp[t] = g_perm[blockIdx.x * 8 + t];
    __syncthreads();

    long long id[8], row[8];
    #pragma unroll
    for (int i = 0; i < 8; ++i) {
        id[i]  = (long long)(sp[i] >> 32);
        row[i] = (long long)(unsigned)sp[i];
    }

    float4 v[8];
    #pragma unroll
    for (int i = 0; i < 8; ++i)
        v[i] = __ldg(w + id[i] * 256 + t);      // all in flight first

    #pragma unroll
    for (int i = 0; i < 8; ++i)
        __stcs(out + row[i] * 256 + t, v[i]);   // evict-first streaming store
}

extern "C" void kernel_launch(void* const* d_in, const int* in_sizes, int n_in,
                              void* d_out, int out_size)
{
    // Resolve input order by element count: weight = 50257*1024, ids = 32768.
    int wi = 0, ii = 1;
    if (in_sizes[0] < in_sizes[1]) { wi = 1; ii = 0; }

    const float4* w   = (const float4*)d_in[wi];
    const int*    ids = (const int*)d_in[ii];
    float4* out = (float4*)d_out;

    k_zero<<<1, N_BUCKETS>>>();
    k_hist<<<N_ROWS / 256, 256>>>(ids);
    k_scan<<<1, N_BUCKETS>>>();
    k_scatter<<<N_ROWS / 256, 256>>>(ids);
    k_gather<<<N_ROWS / 8, 256>>>(w, out);
}

// round 16
// speedup vs baseline: 1.3740x; 1.3740x over previous
#include <cuda_runtime.h>

// out[row, :] = W[ids[row], :]
// W: [50257, 1024] fp32, ids: [32768] int32, out: [32768, 1024] fp32
//
// FINAL (converged, best-measured: 41.44us bench). 8 rows per CTA,
// 256 threads, 8 independent 128-bit gathers per thread, evict-first
// streaming stores. Memory-controller-bound at the mixed read/write
// turnaround ceiling (~5.4 TB/s DRAM on ~190 MB/launch compulsory traffic).
// Closed branches (all measured): MLP depth 1/4/8, 256-bit accesses,
// software pipelining, stwt/evict-hint stores, SMEM id staging (neutral);
// id-ordered gather via bucket sort (-18us regression, R15); L2 persisting
// carveout (forbidden by harness device-limit guard).
__global__ void __launch_bounds__(256)
embed_gather_kernel(const float4* __restrict__ w,
                    const int* __restrict__ ids,
                    float4* __restrict__ out)
{
    const int row0 = blockIdx.x * 8;
    const int t = threadIdx.x;

    long long id[8];
    #pragma unroll
    for (int i = 0; i < 8; ++i)
        id[i] = (long long)ids[row0 + i];   // broadcast loads (L1-resident)

    // 8 independent gathers — all issued before any consumer.
    float4 v[8];
    #pragma unroll
    for (int i = 0; i < 8; ++i)
        v[i] = __ldg(w + id[i] * 256 + t);

    float4* dst = out + (long long)row0 * 256 + t;
    #pragma unroll
    for (int i = 0; i < 8; ++i)
        __stcs(dst + i * 256, v[i]);        // evict-first streaming store
}

extern "C" void kernel_launch(void* const* d_in, const int* in_sizes, int n_in,
                              void* d_out, int out_size)
{
    // Resolve input order by element count: weight = 50257*1024, ids = 32768.
    int wi = 0, ii = 1;
    if (in_sizes[0] < in_sizes[1]) { wi = 1; ii = 0; }

    const float4* w   = (const float4*)d_in[wi];
    const int*    ids = (const int*)d_in[ii];
    const int n_rows  = in_sizes[ii];              // 32768, divisible by 8

    float4* out = (float4*)d_out;
    embed_gather_kernel<<<n_rows / 8, 256>>>(w, ids, out);
}